// round 16
// baseline (speedup 1.0000x reference)
#include <cuda_runtime.h>
#include <cuda_bf16.h>
#include <math.h>
#include <stdint.h>

// Problem constants
#define BB 8
#define LL 1024
#define DD 512
#define HH 8
#define SS 1024
#define SCALE 0.125f

// Output sections (floats): out_re | out_im | attn_re | attn_im
#define OUT_RE_OFF  0UL
#define OUT_IM_OFF  4194304UL
#define ATTN_RE_OFF 8388608UL
#define ATTN_IM_OFF 16777216UL

// Scratch
__device__ float g_sre[(size_t)BB * HH * LL * SS];           // scaled scores re
__device__ float g_sim[(size_t)BB * HH * LL * SS];           // scaled scores im
__device__ __nv_bfloat16 g_p0r[(size_t)BB * HH * LL * SS];   // prob splits
__device__ __nv_bfloat16 g_p1r[(size_t)BB * HH * LL * SS];
__device__ __nv_bfloat16 g_p0i[(size_t)BB * HH * LL * SS];
__device__ __nv_bfloat16 g_p1i[(size_t)BB * HH * LL * SS];
__device__ __nv_bfloat16 g_ps0[(size_t)BB * HH * LL * SS];   // prob sum splits (re+im)
__device__ __nv_bfloat16 g_ps1[(size_t)BB * HH * LL * SS];

// Pre-split input: 6 bf16 arrays [B, L, D] (r_hi, r_lo, i_hi, i_lo, s_hi, s_lo)
#define XN ((size_t)BB * LL * DD)
__device__ __nv_bfloat16 g_xrh[XN], g_xrl[XN];
__device__ __nv_bfloat16 g_xih[XN], g_xil[XN];
__device__ __nv_bfloat16 g_xsh[XN], g_xsl[XN];

// ---------------------------------------------------------------------------
// Helpers (plain sm_80+ PTX only)
// ---------------------------------------------------------------------------
__device__ __forceinline__ uint32_t smem_u32(const void* p) {
    uint32_t a;
    asm("{ .reg .u64 t; cvta.to.shared.u64 t, %1; cvt.u32.u64 %0, t; }"
        : "=r"(a) : "l"(p));
    return a;
}

__device__ __forceinline__ uint32_t pack_bf(__nv_bfloat16 a, __nv_bfloat16 b) {
    __nv_bfloat162 t(a, b);
    return *reinterpret_cast<uint32_t*>(&t);
}

__device__ __forceinline__ void split_pack(float f0, float f1, uint32_t& hi, uint32_t& lo) {
    __nv_bfloat16 h0 = __float2bfloat16(f0), h1 = __float2bfloat16(f1);
    float r0 = f0 - __bfloat162float(h0), r1 = f1 - __bfloat162float(h1);
    hi = pack_bf(h0, h1);
    lo = pack_bf(__float2bfloat16(r0), __float2bfloat16(r1));
}

__device__ __forceinline__ void ldsm4(uint32_t& r0, uint32_t& r1, uint32_t& r2,
                                      uint32_t& r3, uint32_t addr) {
    asm volatile("ldmatrix.sync.aligned.m8n8.x4.shared.b16 {%0,%1,%2,%3}, [%4];"
                 : "=r"(r0), "=r"(r1), "=r"(r2), "=r"(r3) : "r"(addr));
}

__device__ __forceinline__ void ldsm4t(uint32_t& r0, uint32_t& r1, uint32_t& r2,
                                       uint32_t& r3, uint32_t addr) {
    asm volatile("ldmatrix.sync.aligned.m8n8.x4.trans.shared.b16 {%0,%1,%2,%3}, [%4];"
                 : "=r"(r0), "=r"(r1), "=r"(r2), "=r"(r3) : "r"(addr));
}

__device__ __forceinline__ void mma_bf16(float c[4], const uint32_t a[4],
                                         const uint32_t b[2]) {
    asm volatile("mma.sync.aligned.m16n8k16.row.col.f32.bf16.bf16.f32 "
                 "{%0,%1,%2,%3}, {%4,%5,%6,%7}, {%8,%9}, {%0,%1,%2,%3};"
                 : "+f"(c[0]), "+f"(c[1]), "+f"(c[2]), "+f"(c[3])
                 : "r"(a[0]), "r"(a[1]), "r"(a[2]), "r"(a[3]),
                   "r"(b[0]), "r"(b[1]));
}

#define CP16(saddr, gptr) \
    asm volatile("cp.async.cg.shared.global [%0], [%1], 16;" \
                 :: "r"(saddr), "l"(gptr) : "memory")
#define CP_COMMIT() asm volatile("cp.async.commit_group;" ::: "memory")

#define ROWB 144          // 72 bf16 per padded row (K1 tiles)
#define ARR  9216         // one 64x72 bf16 array (K1)
#define BOFF 55296        // K1 B side base

// ---------------------------------------------------------------------------
// K0: pre-split x into 6 bf16 arrays.  Each thread handles 8 elements.
// ---------------------------------------------------------------------------
__global__ void __launch_bounds__(256) k0_split(
    const float* __restrict__ xre, const float* __restrict__ xim)
{
    const size_t base = ((size_t)blockIdx.x * 256 + threadIdx.x) * 8;
    float4 r0 = *(const float4*)(xre + base);
    float4 r1 = *(const float4*)(xre + base + 4);
    float4 i0 = *(const float4*)(xim + base);
    float4 i1 = *(const float4*)(xim + base + 4);
    float fr[8] = { r0.x, r0.y, r0.z, r0.w, r1.x, r1.y, r1.z, r1.w };
    float fi[8] = { i0.x, i0.y, i0.z, i0.w, i1.x, i1.y, i1.z, i1.w };
    uint32_t rh[4], rl[4], ih[4], il[4], sh[4], sl[4];
    #pragma unroll
    for (int j = 0; j < 4; j++) {
        split_pack(fr[2 * j], fr[2 * j + 1], rh[j], rl[j]);
        split_pack(fi[2 * j], fi[2 * j + 1], ih[j], il[j]);
        split_pack(fr[2 * j] + fi[2 * j], fr[2 * j + 1] + fi[2 * j + 1], sh[j], sl[j]);
    }
    *(uint4*)(g_xrh + base) = make_uint4(rh[0], rh[1], rh[2], rh[3]);
    *(uint4*)(g_xrl + base) = make_uint4(rl[0], rl[1], rl[2], rl[3]);
    *(uint4*)(g_xih + base) = make_uint4(ih[0], ih[1], ih[2], ih[3]);
    *(uint4*)(g_xil + base) = make_uint4(il[0], il[1], il[2], il[3]);
    *(uint4*)(g_xsh + base) = make_uint4(sh[0], sh[1], sh[2], sh[3]);
    *(uint4*)(g_xsl + base) = make_uint4(sl[0], sl[1], sl[2], sl[3]);
}

// ---------------------------------------------------------------------------
// K1: symmetric scores via Karatsuba split-MMA.  64x64 tiles, J >= I only,
// mirror-write for J > I.  Fills are pure uint4 copies from pre-split arrays.
// re = (ac - bd)*SCALE ; im = (s - ac - bd)*SCALE.
// ---------------------------------------------------------------------------
#define K1_SMEM 110592

__global__ void __launch_bounds__(256, 2) k1_scores(int dummy)
{
    extern __shared__ char sm_[];
    const uint32_t sb = smem_u32(sm_);
    const int tid = threadIdx.x, wid = tid >> 5, lane = tid & 31;
    const int bh = blockIdx.z, b = bh >> 3, h = bh & 7;

    int t = blockIdx.x, I = 0;
    while (t >= 16 - I) { t -= 16 - I; I++; }
    const int J = I + t;
    const int l0 = I << 6, s0 = J << 6;

    const size_t xbase = (size_t)b * LL * DD + h * 64;
    const __nv_bfloat16* xarr[6] = { g_xrh, g_xrl, g_xih, g_xil, g_xsh, g_xsl };

    #pragma unroll
    for (int i = 0; i < 2; i++) {
        int idx = tid + (i << 8);
        int row = idx >> 3, q = idx & 7;
        uint32_t off = (uint32_t)(row * ROWB + q * 16);
        size_t ga = xbase + (size_t)(l0 + row) * DD + q * 8;
        size_t gb = xbase + (size_t)(s0 + row) * DD + q * 8;
        #pragma unroll
        for (int arr = 0; arr < 6; arr++) {
            *(uint4*)(sm_ + arr * ARR + off)        = *(const uint4*)(xarr[arr] + ga);
            *(uint4*)(sm_ + BOFF + arr * ARR + off) = *(const uint4*)(xarr[arr] + gb);
        }
    }
    __syncthreads();

    const int m0 = (wid >> 2) * 32, n0 = (wid & 3) * 16;
    float acc[3][2][2][4];
    #pragma unroll
    for (int g = 0; g < 3; g++)
        #pragma unroll
        for (int mt = 0; mt < 2; mt++)
            #pragma unroll
            for (int nt = 0; nt < 2; nt++)
                #pragma unroll
                for (int j = 0; j < 4; j++) acc[g][mt][nt][j] = 0.f;

    #pragma unroll
    for (int k0 = 0; k0 < 64; k0 += 16) {
        #pragma unroll
        for (int g = 0; g < 3; g++) {
            uint32_t ah[2][4], al[2][4];
            #pragma unroll
            for (int mt = 0; mt < 2; mt++) {
                uint32_t ad = sb + (2 * g) * ARR +
                    (uint32_t)((m0 + mt * 16 + (lane & 15)) * ROWB +
                               (k0 + ((lane >> 4) << 3)) * 2);
                ldsm4(ah[mt][0], ah[mt][1], ah[mt][2], ah[mt][3], ad);
                ldsm4(al[mt][0], al[mt][1], al[mt][2], al[mt][3], ad + ARR);
            }
            uint32_t bh4[4], bl4[4];
            {
                uint32_t ad = sb + BOFF + (2 * g) * ARR +
                    (uint32_t)((n0 + ((lane >> 4) << 3) + (lane & 7)) * ROWB +
                               (k0 + (((lane >> 3) & 1) << 3)) * 2);
                ldsm4(bh4[0], bh4[1], bh4[2], bh4[3], ad);
                ldsm4(bl4[0], bl4[1], bl4[2], bl4[3], ad + ARR);
            }
            #pragma unroll
            for (int mt = 0; mt < 2; mt++)
                #pragma unroll
                for (int nt = 0; nt < 2; nt++) {
                    uint32_t bh2[2] = { bh4[2 * nt], bh4[2 * nt + 1] };
                    uint32_t bl2[2] = { bl4[2 * nt], bl4[2 * nt + 1] };
                    mma_bf16(acc[g][mt][nt], ah[mt], bh2);
                    mma_bf16(acc[g][mt][nt], ah[mt], bl2);
                    mma_bf16(acc[g][mt][nt], al[mt], bh2);
                }
        }
    }
    __syncthreads();

    float* stre = (float*)sm_;
    float* stim = (float*)(sm_ + 16640);
    #pragma unroll
    for (int mt = 0; mt < 2; mt++)
        #pragma unroll
        for (int nt = 0; nt < 2; nt++) {
            int row = m0 + mt * 16 + (lane >> 2);
            int col = n0 + nt * 8 + ((lane & 3) << 1);
            #pragma unroll
            for (int j = 0; j < 4; j++) {
                float ac = acc[0][mt][nt][j], bd = acc[1][mt][nt][j];
                int so = (row + (j >> 1) * 8) * 65 + col + (j & 1);
                stre[so] = (ac - bd) * SCALE;
                stim[so] = (acc[2][mt][nt][j] - ac - bd) * SCALE;
            }
        }
    __syncthreads();

    #pragma unroll
    for (int i = 0; i < 16; i++) {
        int idx = tid + (i << 8);
        int r = idx >> 6, c = idx & 63;
        g_sre[((size_t)bh * LL + l0 + r) * SS + s0 + c] = stre[r * 65 + c];
        g_sim[((size_t)bh * LL + l0 + r) * SS + s0 + c] = stim[r * 65 + c];
    }
    if (J > I) {
        #pragma unroll
        for (int i = 0; i < 16; i++) {
            int idx = tid + (i << 8);
            int r = idx >> 6, c = idx & 63;
            g_sre[((size_t)bh * LL + s0 + r) * SS + l0 + c] = stre[c * 65 + r];
            g_sim[((size_t)bh * LL + s0 + r) * SS + l0 + c] = stim[c * 65 + r];
        }
    }
}

// ---------------------------------------------------------------------------
// K2: warp-per-head softmax + head-mean.  Emits bf16 split prob pairs AND
// sum splits (re+im) so K3's fill needs zero ALU.
// ---------------------------------------------------------------------------
__global__ void __launch_bounds__(256) k_softmax(float* __restrict__ out)
{
    extern __shared__ float psm[];      // pr[8][1024] | pi[8][1024]
    float* pr = psm;
    float* pi = psm + 8 * 1024;

    const int bl = blockIdx.x;
    const int tid = threadIdx.x;
    const int w = tid >> 5, ln = tid & 31;
    const int b = bl >> 10, l = bl & 1023;

    {
        const size_t base = (((size_t)(b * HH + w)) * LL + l) * SS;
        float4 vr[8], vi[8];
        #pragma unroll
        for (int j = 0; j < 8; j++) {
            size_t off = base + (size_t)(j * 128 + (ln << 2));
            vr[j] = *(const float4*)(g_sre + off);
            vi[j] = *(const float4*)(g_sim + off);
        }
        float mr = -3.4e38f, mi = -3.4e38f;
        #pragma unroll
        for (int j = 0; j < 8; j++) {
            mr = fmaxf(mr, fmaxf(fmaxf(vr[j].x, vr[j].y), fmaxf(vr[j].z, vr[j].w)));
            mi = fmaxf(mi, fmaxf(fmaxf(vi[j].x, vi[j].y), fmaxf(vi[j].z, vi[j].w)));
        }
        #pragma unroll
        for (int o = 16; o; o >>= 1) {
            mr = fmaxf(mr, __shfl_xor_sync(0xffffffffu, mr, o));
            mi = fmaxf(mi, __shfl_xor_sync(0xffffffffu, mi, o));
        }
        float sr = 0.f, si = 0.f;
        #pragma unroll
        for (int j = 0; j < 8; j++) {
            vr[j].x = __expf(vr[j].x - mr); vr[j].y = __expf(vr[j].y - mr);
            vr[j].z = __expf(vr[j].z - mr); vr[j].w = __expf(vr[j].w - mr);
            vi[j].x = __expf(vi[j].x - mi); vi[j].y = __expf(vi[j].y - mi);
            vi[j].z = __expf(vi[j].z - mi); vi[j].w = __expf(vi[j].w - mi);
            sr += vr[j].x + vr[j].y + vr[j].z + vr[j].w;
            si += vi[j].x + vi[j].y + vi[j].z + vi[j].w;
        }
        #pragma unroll
        for (int o = 16; o; o >>= 1) {
            sr += __shfl_xor_sync(0xffffffffu, sr, o);
            si += __shfl_xor_sync(0xffffffffu, si, o);
        }
        const float inr = 1.0f / sr, ini = 1.0f / si;
        #pragma unroll
        for (int j = 0; j < 8; j++) {
            vr[j].x *= inr; vr[j].y *= inr; vr[j].z *= inr; vr[j].w *= inr;
            vi[j].x *= ini; vi[j].y *= ini; vi[j].z *= ini; vi[j].w *= ini;
            size_t off = base + (size_t)(j * 128 + (ln << 2));
            uint32_t h01, l01, h23, l23;
            split_pack(vr[j].x, vr[j].y, h01, l01);
            split_pack(vr[j].z, vr[j].w, h23, l23);
            *(uint32_t*)(g_p0r + off)     = h01;
            *(uint32_t*)(g_p0r + off + 2) = h23;
            *(uint32_t*)(g_p1r + off)     = l01;
            *(uint32_t*)(g_p1r + off + 2) = l23;
            split_pack(vi[j].x, vi[j].y, h01, l01);
            split_pack(vi[j].z, vi[j].w, h23, l23);
            *(uint32_t*)(g_p0i + off)     = h01;
            *(uint32_t*)(g_p0i + off + 2) = h23;
            *(uint32_t*)(g_p1i + off)     = l01;
            *(uint32_t*)(g_p1i + off + 2) = l23;
            split_pack(vr[j].x + vi[j].x, vr[j].y + vi[j].y, h01, l01);
            split_pack(vr[j].z + vi[j].z, vr[j].w + vi[j].w, h23, l23);
            *(uint32_t*)(g_ps0 + off)     = h01;
            *(uint32_t*)(g_ps0 + off + 2) = h23;
            *(uint32_t*)(g_ps1 + off)     = l01;
            *(uint32_t*)(g_ps1 + off + 2) = l23;
            int so = w * 1024 + j * 128 + (ln << 2);
            *(float4*)(pr + so) = vr[j];
            *(float4*)(pi + so) = vi[j];
        }
    }
    __syncthreads();

    float4 ar = make_float4(0.f, 0.f, 0.f, 0.f);
    float4 ai = make_float4(0.f, 0.f, 0.f, 0.f);
    #pragma unroll
    for (int hh = 0; hh < HH; hh++) {
        float4 r = *(const float4*)(pr + hh * 1024 + (tid << 2));
        float4 m = *(const float4*)(pi + hh * 1024 + (tid << 2));
        ar.x += r.x; ar.y += r.y; ar.z += r.z; ar.w += r.w;
        ai.x += m.x; ai.y += m.y; ai.z += m.z; ai.w += m.w;
    }
    const float wgt = 1.0f / (float)HH;
    ar.x *= wgt; ar.y *= wgt; ar.z *= wgt; ar.w *= wgt;
    ai.x *= wgt; ai.y *= wgt; ai.z *= wgt; ai.w *= wgt;
    size_t ao = (size_t)bl * SS + ((size_t)tid << 2);
    *(float4*)(out + ATTN_RE_OFF + ao) = ar;
    *(float4*)(out + ATTN_IM_OFF + ao) = ai;
}

// ---------------------------------------------------------------------------
// K3: output via Karatsuba split-MMA, cp.async double-buffered, 2 CTAs/SM.
// CTA tile 64(l) x 64(d), K = S = 1024 in 32 chunks of 32.
// A arrays: 64 l x 32 s, 64B rows, XOR swizzle q^(l&3) (4096 B each).
// V arrays: 32 s x 64 d, 128B rows, XOR swizzle q^(s&7) (4096 B each).
// Stage = 12 x 4096 = 49152 B; 2 stages = 98304 -> 2 CTAs/SM.
// o_re = ac - bd ; o_im = s - ac - bd.
// ---------------------------------------------------------------------------
#define K3_STG  49152
#define K3_VOFF 24576
#define K3_SMEM 98304

__global__ void __launch_bounds__(256, 2) k3_out(float* __restrict__ out)
{
    extern __shared__ char sm_[];
    const uint32_t sb = smem_u32(sm_);
    const int tid = threadIdx.x, wid = tid >> 5, lane = tid & 31;
    const int bh = blockIdx.y, b = bh >> 3, h = bh & 7;
    const int l0 = blockIdx.x << 6;

    const size_t xbase = (size_t)b * LL * DD + h * 64;
    const __nv_bfloat16* aarr[6] = { g_p0r, g_p1r, g_p0i, g_p1i, g_ps0, g_ps1 };
    const __nv_bfloat16* varr[6] = { g_xrh, g_xrl, g_xih, g_xil, g_xsh, g_xsl };
    const size_t abase = (size_t)bh * LL + l0;

    const int m0 = (wid >> 2) * 32, n0q = (wid & 3) << 1;   // n qword base
    float acc[3][2][2][4];
    #pragma unroll
    for (int g = 0; g < 3; g++)
        #pragma unroll
        for (int mt = 0; mt < 2; mt++)
            #pragma unroll
            for (int nt = 0; nt < 2; nt++)
                #pragma unroll
                for (int j = 0; j < 4; j++) acc[g][mt][nt][j] = 0.f;

    // A fill: 256 qwords per array (64 rows x 4 q); V: 256 (32 rows x 8 q).
    const int arow = tid >> 2, aq = tid & 3;
    const int vrow = tid >> 3, vq = tid & 7;
    const uint32_t aoff = (uint32_t)(arow * 64 + ((aq ^ (arow & 3)) << 4));
    const uint32_t voff = (uint32_t)(K3_VOFF + vrow * 128 + ((vq ^ (vrow & 7)) << 4));

    auto fill = [&](int c, int st) {
        const uint32_t stb = sb + st * K3_STG;
        const size_t ga = (abase + arow) * SS + c * 32 + aq * 8;
        const size_t gv = xbase + (size_t)(c * 32 + vrow) * DD + vq * 8;
        #pragma unroll
        for (int arr = 0; arr < 6; arr++) {
            CP16(stb + arr * 4096 + aoff, aarr[arr] + ga);
            CP16(stb + voff + arr * 4096, varr[arr] + gv);
        }
        CP_COMMIT();
    };

    fill(0, 0);

    for (int c = 0; c < 32; c++) {
        const int st = c & 1;
        if (c < 31) fill(c + 1, st ^ 1);
        if (c < 31) asm volatile("cp.async.wait_group 1;" ::: "memory");
        else        asm volatile("cp.async.wait_group 0;" ::: "memory");
        __syncthreads();

        const uint32_t stb = sb + st * K3_STG;
        #pragma unroll
        for (int k0 = 0; k0 < 32; k0 += 16) {
            #pragma unroll
            for (int g = 0; g < 3; g++) {
                uint32_t ah[2][4], al[2][4];
                #pragma unroll
                for (int mt = 0; mt < 2; mt++) {
                    int l_ = m0 + mt * 16 + (lane & 15);
                    int q  = (k0 >> 3) + (lane >> 4);
                    uint32_t ad = stb + (2 * g) * 4096 +
                        (uint32_t)(l_ * 64 + ((q ^ (l_ & 3)) << 4));
                    ldsm4(ah[mt][0], ah[mt][1], ah[mt][2], ah[mt][3], ad);
                    ldsm4(al[mt][0], al[mt][1], al[mt][2], al[mt][3], ad + 4096);
                }
                uint32_t bh4[4], bl4[4];
                {
                    int s_ = k0 + (((lane >> 3) & 1) << 3) + (lane & 7);
                    int q  = n0q + (lane >> 4);
                    uint32_t ad = stb + K3_VOFF + (2 * g) * 4096 +
                        (uint32_t)(s_ * 128 + ((q ^ (s_ & 7)) << 4));
                    ldsm4t(bh4[0], bh4[1], bh4[2], bh4[3], ad);
                    ldsm4t(bl4[0], bl4[1], bl4[2], bl4[3], ad + 4096);
                }
                #pragma unroll
                for (int mt = 0; mt < 2; mt++)
                    #pragma unroll
                    for (int nt = 0; nt < 2; nt++) {
                        uint32_t bh2[2] = { bh4[2 * nt], bh4[2 * nt + 1] };
                        uint32_t bl2[2] = { bl4[2 * nt], bl4[2 * nt + 1] };
                        mma_bf16(acc[g][mt][nt], ah[mt], bh2);
                        mma_bf16(acc[g][mt][nt], ah[mt], bl2);
                        mma_bf16(acc[g][mt][nt], al[mt], bh2);
                    }
            }
        }
        __syncthreads();   // stage st reusable at c+2
    }

    // Epilogue: direct float2 stores
    const int n0 = (wid & 3) * 16;
    #pragma unroll
    for (int mt = 0; mt < 2; mt++)
        #pragma unroll
        for (int nt = 0; nt < 2; nt++) {
            int row = l0 + m0 + mt * 16 + (lane >> 2);
            int col = h * 64 + n0 + nt * 8 + ((lane & 3) << 1);
            size_t base = ((size_t)b * LL + row) * DD + col;
            float* ac = acc[0][mt][nt];
            float* bd = acc[1][mt][nt];
            float* s  = acc[2][mt][nt];
            *(float2*)(out + OUT_RE_OFF + base) =
                make_float2(ac[0] - bd[0], ac[1] - bd[1]);
            *(float2*)(out + OUT_RE_OFF + base + 8 * DD) =
                make_float2(ac[2] - bd[2], ac[3] - bd[3]);
            *(float2*)(out + OUT_IM_OFF + base) =
                make_float2(s[0] - ac[0] - bd[0], s[1] - ac[1] - bd[1]);
            *(float2*)(out + OUT_IM_OFF + base + 8 * DD) =
                make_float2(s[2] - ac[2] - bd[2], s[3] - ac[3] - bd[3]);
        }
}

// ---------------------------------------------------------------------------
extern "C" void kernel_launch(void* const* d_in, const int* in_sizes, int n_in,
                              void* d_out, int out_size)
{
    const float* xre = (const float*)d_in[0];
    const float* xim = (const float*)d_in[1];
    float* outp = (float*)d_out;

    const int smem2 = 2 * 8 * 1024 * 4;  // 65536
    cudaFuncSetAttribute(k1_scores, cudaFuncAttributeMaxDynamicSharedMemorySize, K1_SMEM);
    cudaFuncSetAttribute(k_softmax, cudaFuncAttributeMaxDynamicSharedMemorySize, smem2);
    cudaFuncSetAttribute(k3_out,    cudaFuncAttributeMaxDynamicSharedMemorySize, K3_SMEM);

    k0_split<<<2048, 256>>>(xre, xim);
    k1_scores<<<dim3(136, 1, 64), 256, K1_SMEM>>>(0);
    k_softmax<<<BB * LL, 256, smem2>>>(outp);
    k3_out<<<dim3(16, 64), 256, K3_SMEM>>>(outp);
}

// round 17
// speedup vs baseline: 1.1781x; 1.1781x over previous
#include <cuda_runtime.h>
#include <cuda_bf16.h>
#include <math.h>
#include <stdint.h>

// Problem constants
#define BB 8
#define LL 1024
#define DD 512
#define HH 8
#define SS 1024
#define SCALE 0.125f

// Output sections (floats): out_re | out_im | attn_re | attn_im
#define OUT_RE_OFF  0UL
#define OUT_IM_OFF  4194304UL
#define ATTN_RE_OFF 8388608UL
#define ATTN_IM_OFF 16777216UL

// Scratch
__device__ float g_sre[(size_t)BB * HH * LL * SS];           // scaled scores re
__device__ float g_sim[(size_t)BB * HH * LL * SS];           // scaled scores im
__device__ __nv_bfloat16 g_p0r[(size_t)BB * HH * LL * SS];   // prob splits
__device__ __nv_bfloat16 g_p1r[(size_t)BB * HH * LL * SS];
__device__ __nv_bfloat16 g_p0i[(size_t)BB * HH * LL * SS];
__device__ __nv_bfloat16 g_p1i[(size_t)BB * HH * LL * SS];

// Pre-split input: 6 bf16 arrays [B, L, D] (r_hi, r_lo, i_hi, i_lo, s_hi, s_lo)
// (s arrays used by K1's Karatsuba only)
#define XN ((size_t)BB * LL * DD)
__device__ __nv_bfloat16 g_xrh[XN], g_xrl[XN];
__device__ __nv_bfloat16 g_xih[XN], g_xil[XN];
__device__ __nv_bfloat16 g_xsh[XN], g_xsl[XN];

// ---------------------------------------------------------------------------
// Helpers (plain sm_80+ PTX only)
// ---------------------------------------------------------------------------
__device__ __forceinline__ uint32_t smem_u32(const void* p) {
    uint32_t a;
    asm("{ .reg .u64 t; cvta.to.shared.u64 t, %1; cvt.u32.u64 %0, t; }"
        : "=r"(a) : "l"(p));
    return a;
}

__device__ __forceinline__ uint32_t pack_bf(__nv_bfloat16 a, __nv_bfloat16 b) {
    __nv_bfloat162 t(a, b);
    return *reinterpret_cast<uint32_t*>(&t);
}

__device__ __forceinline__ void split_pack(float f0, float f1, uint32_t& hi, uint32_t& lo) {
    __nv_bfloat16 h0 = __float2bfloat16(f0), h1 = __float2bfloat16(f1);
    float r0 = f0 - __bfloat162float(h0), r1 = f1 - __bfloat162float(h1);
    hi = pack_bf(h0, h1);
    lo = pack_bf(__float2bfloat16(r0), __float2bfloat16(r1));
}

__device__ __forceinline__ void ldsm4(uint32_t& r0, uint32_t& r1, uint32_t& r2,
                                      uint32_t& r3, uint32_t addr) {
    asm volatile("ldmatrix.sync.aligned.m8n8.x4.shared.b16 {%0,%1,%2,%3}, [%4];"
                 : "=r"(r0), "=r"(r1), "=r"(r2), "=r"(r3) : "r"(addr));
}

__device__ __forceinline__ void ldsm4t(uint32_t& r0, uint32_t& r1, uint32_t& r2,
                                       uint32_t& r3, uint32_t addr) {
    asm volatile("ldmatrix.sync.aligned.m8n8.x4.trans.shared.b16 {%0,%1,%2,%3}, [%4];"
                 : "=r"(r0), "=r"(r1), "=r"(r2), "=r"(r3) : "r"(addr));
}

__device__ __forceinline__ void mma_bf16(float c[4], const uint32_t a[4],
                                         const uint32_t b[2]) {
    asm volatile("mma.sync.aligned.m16n8k16.row.col.f32.bf16.bf16.f32 "
                 "{%0,%1,%2,%3}, {%4,%5,%6,%7}, {%8,%9}, {%0,%1,%2,%3};"
                 : "+f"(c[0]), "+f"(c[1]), "+f"(c[2]), "+f"(c[3])
                 : "r"(a[0]), "r"(a[1]), "r"(a[2]), "r"(a[3]),
                   "r"(b[0]), "r"(b[1]));
}

#define CP16(saddr, gptr) \
    asm volatile("cp.async.cg.shared.global [%0], [%1], 16;" \
                 :: "r"(saddr), "l"(gptr) : "memory")
#define CP_COMMIT() asm volatile("cp.async.commit_group;" ::: "memory")

#define ROWB 144          // 72 bf16 per padded row (K1 tiles)
#define ARR  9216         // one 64x72 bf16 array (K1)
#define BOFF 55296        // K1 B side base

// ---------------------------------------------------------------------------
// K0: pre-split x into 6 bf16 arrays.  Each thread handles 8 elements.
// ---------------------------------------------------------------------------
__global__ void __launch_bounds__(256) k0_split(
    const float* __restrict__ xre, const float* __restrict__ xim)
{
    const size_t base = ((size_t)blockIdx.x * 256 + threadIdx.x) * 8;
    float4 r0 = *(const float4*)(xre + base);
    float4 r1 = *(const float4*)(xre + base + 4);
    float4 i0 = *(const float4*)(xim + base);
    float4 i1 = *(const float4*)(xim + base + 4);
    float fr[8] = { r0.x, r0.y, r0.z, r0.w, r1.x, r1.y, r1.z, r1.w };
    float fi[8] = { i0.x, i0.y, i0.z, i0.w, i1.x, i1.y, i1.z, i1.w };
    uint32_t rh[4], rl[4], ih[4], il[4], sh[4], sl[4];
    #pragma unroll
    for (int j = 0; j < 4; j++) {
        split_pack(fr[2 * j], fr[2 * j + 1], rh[j], rl[j]);
        split_pack(fi[2 * j], fi[2 * j + 1], ih[j], il[j]);
        split_pack(fr[2 * j] + fi[2 * j], fr[2 * j + 1] + fi[2 * j + 1], sh[j], sl[j]);
    }
    *(uint4*)(g_xrh + base) = make_uint4(rh[0], rh[1], rh[2], rh[3]);
    *(uint4*)(g_xrl + base) = make_uint4(rl[0], rl[1], rl[2], rl[3]);
    *(uint4*)(g_xih + base) = make_uint4(ih[0], ih[1], ih[2], ih[3]);
    *(uint4*)(g_xil + base) = make_uint4(il[0], il[1], il[2], il[3]);
    *(uint4*)(g_xsh + base) = make_uint4(sh[0], sh[1], sh[2], sh[3]);
    *(uint4*)(g_xsl + base) = make_uint4(sl[0], sl[1], sl[2], sl[3]);
}

// ---------------------------------------------------------------------------
// K1: symmetric scores via Karatsuba split-MMA.  64x64 tiles, J >= I only,
// mirror-write for J > I.  Fills are pure uint4 copies from pre-split arrays.
// re = (ac - bd)*SCALE ; im = (s - ac - bd)*SCALE.
// ---------------------------------------------------------------------------
#define K1_SMEM 110592

__global__ void __launch_bounds__(256, 2) k1_scores(int dummy)
{
    extern __shared__ char sm_[];
    const uint32_t sb = smem_u32(sm_);
    const int tid = threadIdx.x, wid = tid >> 5, lane = tid & 31;
    const int bh = blockIdx.z, b = bh >> 3, h = bh & 7;

    int t = blockIdx.x, I = 0;
    while (t >= 16 - I) { t -= 16 - I; I++; }
    const int J = I + t;
    const int l0 = I << 6, s0 = J << 6;

    const size_t xbase = (size_t)b * LL * DD + h * 64;
    const __nv_bfloat16* xarr[6] = { g_xrh, g_xrl, g_xih, g_xil, g_xsh, g_xsl };

    #pragma unroll
    for (int i = 0; i < 2; i++) {
        int idx = tid + (i << 8);
        int row = idx >> 3, q = idx & 7;
        uint32_t off = (uint32_t)(row * ROWB + q * 16);
        size_t ga = xbase + (size_t)(l0 + row) * DD + q * 8;
        size_t gb = xbase + (size_t)(s0 + row) * DD + q * 8;
        #pragma unroll
        for (int arr = 0; arr < 6; arr++) {
            *(uint4*)(sm_ + arr * ARR + off)        = *(const uint4*)(xarr[arr] + ga);
            *(uint4*)(sm_ + BOFF + arr * ARR + off) = *(const uint4*)(xarr[arr] + gb);
        }
    }
    __syncthreads();

    const int m0 = (wid >> 2) * 32, n0 = (wid & 3) * 16;
    float acc[3][2][2][4];
    #pragma unroll
    for (int g = 0; g < 3; g++)
        #pragma unroll
        for (int mt = 0; mt < 2; mt++)
            #pragma unroll
            for (int nt = 0; nt < 2; nt++)
                #pragma unroll
                for (int j = 0; j < 4; j++) acc[g][mt][nt][j] = 0.f;

    #pragma unroll
    for (int k0 = 0; k0 < 64; k0 += 16) {
        #pragma unroll
        for (int g = 0; g < 3; g++) {
            uint32_t ah[2][4], al[2][4];
            #pragma unroll
            for (int mt = 0; mt < 2; mt++) {
                uint32_t ad = sb + (2 * g) * ARR +
                    (uint32_t)((m0 + mt * 16 + (lane & 15)) * ROWB +
                               (k0 + ((lane >> 4) << 3)) * 2);
                ldsm4(ah[mt][0], ah[mt][1], ah[mt][2], ah[mt][3], ad);
                ldsm4(al[mt][0], al[mt][1], al[mt][2], al[mt][3], ad + ARR);
            }
            uint32_t bh4[4], bl4[4];
            {
                uint32_t ad = sb + BOFF + (2 * g) * ARR +
                    (uint32_t)((n0 + ((lane >> 4) << 3) + (lane & 7)) * ROWB +
                               (k0 + (((lane >> 3) & 1) << 3)) * 2);
                ldsm4(bh4[0], bh4[1], bh4[2], bh4[3], ad);
                ldsm4(bl4[0], bl4[1], bl4[2], bl4[3], ad + ARR);
            }
            #pragma unroll
            for (int mt = 0; mt < 2; mt++)
                #pragma unroll
                for (int nt = 0; nt < 2; nt++) {
                    uint32_t bh2[2] = { bh4[2 * nt], bh4[2 * nt + 1] };
                    uint32_t bl2[2] = { bl4[2 * nt], bl4[2 * nt + 1] };
                    mma_bf16(acc[g][mt][nt], ah[mt], bh2);
                    mma_bf16(acc[g][mt][nt], ah[mt], bl2);
                    mma_bf16(acc[g][mt][nt], al[mt], bh2);
                }
        }
    }
    __syncthreads();

    float* stre = (float*)sm_;
    float* stim = (float*)(sm_ + 16640);
    #pragma unroll
    for (int mt = 0; mt < 2; mt++)
        #pragma unroll
        for (int nt = 0; nt < 2; nt++) {
            int row = m0 + mt * 16 + (lane >> 2);
            int col = n0 + nt * 8 + ((lane & 3) << 1);
            #pragma unroll
            for (int j = 0; j < 4; j++) {
                float ac = acc[0][mt][nt][j], bd = acc[1][mt][nt][j];
                int so = (row + (j >> 1) * 8) * 65 + col + (j & 1);
                stre[so] = (ac - bd) * SCALE;
                stim[so] = (acc[2][mt][nt][j] - ac - bd) * SCALE;
            }
        }
    __syncthreads();

    #pragma unroll
    for (int i = 0; i < 16; i++) {
        int idx = tid + (i << 8);
        int r = idx >> 6, c = idx & 63;
        g_sre[((size_t)bh * LL + l0 + r) * SS + s0 + c] = stre[r * 65 + c];
        g_sim[((size_t)bh * LL + l0 + r) * SS + s0 + c] = stim[r * 65 + c];
    }
    if (J > I) {
        #pragma unroll
        for (int i = 0; i < 16; i++) {
            int idx = tid + (i << 8);
            int r = idx >> 6, c = idx & 63;
            g_sre[((size_t)bh * LL + s0 + r) * SS + l0 + c] = stre[c * 65 + r];
            g_sim[((size_t)bh * LL + s0 + r) * SS + l0 + c] = stim[c * 65 + r];
        }
    }
}

// ---------------------------------------------------------------------------
// K2: warp-per-head softmax + head-mean.  Emits bf16 split prob pairs
// (no sum splits — K3 uses the 4-product form).
// ---------------------------------------------------------------------------
__global__ void __launch_bounds__(256) k_softmax(float* __restrict__ out)
{
    extern __shared__ float psm[];      // pr[8][1024] | pi[8][1024]
    float* pr = psm;
    float* pi = psm + 8 * 1024;

    const int bl = blockIdx.x;
    const int tid = threadIdx.x;
    const int w = tid >> 5, ln = tid & 31;
    const int b = bl >> 10, l = bl & 1023;

    {
        const size_t base = (((size_t)(b * HH + w)) * LL + l) * SS;
        float4 vr[8], vi[8];
        #pragma unroll
        for (int j = 0; j < 8; j++) {
            size_t off = base + (size_t)(j * 128 + (ln << 2));
            vr[j] = *(const float4*)(g_sre + off);
            vi[j] = *(const float4*)(g_sim + off);
        }
        float mr = -3.4e38f, mi = -3.4e38f;
        #pragma unroll
        for (int j = 0; j < 8; j++) {
            mr = fmaxf(mr, fmaxf(fmaxf(vr[j].x, vr[j].y), fmaxf(vr[j].z, vr[j].w)));
            mi = fmaxf(mi, fmaxf(fmaxf(vi[j].x, vi[j].y), fmaxf(vi[j].z, vi[j].w)));
        }
        #pragma unroll
        for (int o = 16; o; o >>= 1) {
            mr = fmaxf(mr, __shfl_xor_sync(0xffffffffu, mr, o));
            mi = fmaxf(mi, __shfl_xor_sync(0xffffffffu, mi, o));
        }
        float sr = 0.f, si = 0.f;
        #pragma unroll
        for (int j = 0; j < 8; j++) {
            vr[j].x = __expf(vr[j].x - mr); vr[j].y = __expf(vr[j].y - mr);
            vr[j].z = __expf(vr[j].z - mr); vr[j].w = __expf(vr[j].w - mr);
            vi[j].x = __expf(vi[j].x - mi); vi[j].y = __expf(vi[j].y - mi);
            vi[j].z = __expf(vi[j].z - mi); vi[j].w = __expf(vi[j].w - mi);
            sr += vr[j].x + vr[j].y + vr[j].z + vr[j].w;
            si += vi[j].x + vi[j].y + vi[j].z + vi[j].w;
        }
        #pragma unroll
        for (int o = 16; o; o >>= 1) {
            sr += __shfl_xor_sync(0xffffffffu, sr, o);
            si += __shfl_xor_sync(0xffffffffu, si, o);
        }
        const float inr = 1.0f / sr, ini = 1.0f / si;
        #pragma unroll
        for (int j = 0; j < 8; j++) {
            vr[j].x *= inr; vr[j].y *= inr; vr[j].z *= inr; vr[j].w *= inr;
            vi[j].x *= ini; vi[j].y *= ini; vi[j].z *= ini; vi[j].w *= ini;
            size_t off = base + (size_t)(j * 128 + (ln << 2));
            uint32_t h01, l01, h23, l23;
            split_pack(vr[j].x, vr[j].y, h01, l01);
            split_pack(vr[j].z, vr[j].w, h23, l23);
            *(uint32_t*)(g_p0r + off)     = h01;
            *(uint32_t*)(g_p0r + off + 2) = h23;
            *(uint32_t*)(g_p1r + off)     = l01;
            *(uint32_t*)(g_p1r + off + 2) = l23;
            split_pack(vi[j].x, vi[j].y, h01, l01);
            split_pack(vi[j].z, vi[j].w, h23, l23);
            *(uint32_t*)(g_p0i + off)     = h01;
            *(uint32_t*)(g_p0i + off + 2) = h23;
            *(uint32_t*)(g_p1i + off)     = l01;
            *(uint32_t*)(g_p1i + off + 2) = l23;
            int so = w * 1024 + j * 128 + (ln << 2);
            *(float4*)(pr + so) = vr[j];
            *(float4*)(pi + so) = vi[j];
        }
    }
    __syncthreads();

    float4 ar = make_float4(0.f, 0.f, 0.f, 0.f);
    float4 ai = make_float4(0.f, 0.f, 0.f, 0.f);
    #pragma unroll
    for (int hh = 0; hh < HH; hh++) {
        float4 r = *(const float4*)(pr + hh * 1024 + (tid << 2));
        float4 m = *(const float4*)(pi + hh * 1024 + (tid << 2));
        ar.x += r.x; ar.y += r.y; ar.z += r.z; ar.w += r.w;
        ai.x += m.x; ai.y += m.y; ai.z += m.z; ai.w += m.w;
    }
    const float wgt = 1.0f / (float)HH;
    ar.x *= wgt; ar.y *= wgt; ar.z *= wgt; ar.w *= wgt;
    ai.x *= wgt; ai.y *= wgt; ai.z *= wgt; ai.w *= wgt;
    size_t ao = (size_t)bl * SS + ((size_t)tid << 2);
    *(float4*)(out + ATTN_RE_OFF + ao) = ar;
    *(float4*)(out + ATTN_IM_OFF + ao) = ai;
}

// ---------------------------------------------------------------------------
// K3: output via 4-product split-MMA, cp.async double-buffered, 2 CTAs/SM.
// CTA tile 64(l) x 64(d), K = S = 1024 in 32 chunks of 32.
// Only 8 operand arrays (4 A prob splits + 4 V x splits) -> 32KB/chunk fill.
// A arrays: 64 l x 32 s, 64B rows, swizzle q^((l>>1)&3)  -> conflict-free.
// V arrays: 32 s x 64 d, 128B rows, swizzle q^(s&7)      -> conflict-free.
// Stage = 8 x 4096 = 32768 B; 2 stages = 65536 -> 2 CTAs/SM.
// Accumulators: D+ = Ar·Vr, D- = Ai·Vi, Dim = Ar·Vi + Ai·Vr.
// o_re = D+ - D- ; o_im = Dim.
// ---------------------------------------------------------------------------
#define K3_STG  32768
#define K3_VOFF 16384
#define K3_SMEM 65536

__global__ void __launch_bounds__(256, 2) k3_out(float* __restrict__ out)
{
    extern __shared__ char sm_[];
    const uint32_t sb = smem_u32(sm_);
    const int tid = threadIdx.x, wid = tid >> 5, lane = tid & 31;
    const int bh = blockIdx.y, b = bh >> 3, h = bh & 7;
    const int l0 = blockIdx.x << 6;

    const size_t xbase = (size_t)b * LL * DD + h * 64;
    const __nv_bfloat16* aarr[4] = { g_p0r, g_p1r, g_p0i, g_p1i };
    const __nv_bfloat16* varr[4] = { g_xrh, g_xrl, g_xih, g_xil };
    const size_t abase = (size_t)bh * LL + l0;

    const int m0 = (wid >> 2) * 32, n0q = (wid & 3) << 1;
    float acc[3][2][2][4];
    #pragma unroll
    for (int g = 0; g < 3; g++)
        #pragma unroll
        for (int mt = 0; mt < 2; mt++)
            #pragma unroll
            for (int nt = 0; nt < 2; nt++)
                #pragma unroll
                for (int j = 0; j < 4; j++) acc[g][mt][nt][j] = 0.f;

    const int arow = tid >> 2, aq = tid & 3;
    const int vrow = tid >> 3, vq = tid & 7;
    const uint32_t aoff = (uint32_t)(arow * 64 + ((aq ^ ((arow >> 1) & 3)) << 4));
    const uint32_t voff = (uint32_t)(K3_VOFF + vrow * 128 + ((vq ^ (vrow & 7)) << 4));

    auto fill = [&](int c, int st) {
        const uint32_t stb = sb + st * K3_STG;
        const size_t ga = (abase + arow) * SS + c * 32 + aq * 8;
        const size_t gv = xbase + (size_t)(c * 32 + vrow) * DD + vq * 8;
        #pragma unroll
        for (int arr = 0; arr < 4; arr++) {
            CP16(stb + arr * 4096 + aoff, aarr[arr] + ga);
            CP16(stb + voff + arr * 4096, varr[arr] + gv);
        }
        CP_COMMIT();
    };

    fill(0, 0);

    for (int c = 0; c < 32; c++) {
        const int st = c & 1;
        if (c < 31) fill(c + 1, st ^ 1);
        if (c < 31) asm volatile("cp.async.wait_group 1;" ::: "memory");
        else        asm volatile("cp.async.wait_group 0;" ::: "memory");
        __syncthreads();

        const uint32_t stb = sb + st * K3_STG;
        #pragma unroll
        for (int k0 = 0; k0 < 32; k0 += 16) {
            // A fragments: [arr 0..3][mt][4]   (Ar_h, Ar_l, Ai_h, Ai_l)
            uint32_t a[4][2][4];
            #pragma unroll
            for (int arr = 0; arr < 4; arr++)
                #pragma unroll
                for (int mt = 0; mt < 2; mt++) {
                    int l_ = m0 + mt * 16 + (lane & 15);
                    int q  = (k0 >> 3) + (lane >> 4);
                    uint32_t ad = stb + arr * 4096 +
                        (uint32_t)(l_ * 64 + ((q ^ ((l_ >> 1) & 3)) << 4));
                    ldsm4(a[arr][mt][0], a[arr][mt][1], a[arr][mt][2], a[arr][mt][3], ad);
                }
            // B fragments: [arr 0..3][nt][2]   (Vr_h, Vr_l, Vi_h, Vi_l)
            uint32_t bf[4][2][2];
            #pragma unroll
            for (int arr = 0; arr < 4; arr++) {
                int s_ = k0 + (((lane >> 3) & 1) << 3) + (lane & 7);
                int q  = n0q + (lane >> 4);
                uint32_t ad = stb + K3_VOFF + arr * 4096 +
                    (uint32_t)(s_ * 128 + ((q ^ (s_ & 7)) << 4));
                uint32_t r0, r1, r2, r3;
                ldsm4t(r0, r1, r2, r3, ad);
                bf[arr][0][0] = r0; bf[arr][0][1] = r1;
                bf[arr][1][0] = r2; bf[arr][1][1] = r3;
            }
            #pragma unroll
            for (int mt = 0; mt < 2; mt++)
                #pragma unroll
                for (int nt = 0; nt < 2; nt++) {
                    // D+ = Ar·Vr (hi*hi, hi*lo, lo*hi)
                    mma_bf16(acc[0][mt][nt], a[0][mt], bf[0][nt]);
                    mma_bf16(acc[0][mt][nt], a[0][mt], bf[1][nt]);
                    mma_bf16(acc[0][mt][nt], a[1][mt], bf[0][nt]);
                    // D- = Ai·Vi
                    mma_bf16(acc[1][mt][nt], a[2][mt], bf[2][nt]);
                    mma_bf16(acc[1][mt][nt], a[2][mt], bf[3][nt]);
                    mma_bf16(acc[1][mt][nt], a[3][mt], bf[2][nt]);
                    // Dim = Ar·Vi + Ai·Vr
                    mma_bf16(acc[2][mt][nt], a[0][mt], bf[2][nt]);
                    mma_bf16(acc[2][mt][nt], a[0][mt], bf[3][nt]);
                    mma_bf16(acc[2][mt][nt], a[1][mt], bf[2][nt]);
                    mma_bf16(acc[2][mt][nt], a[2][mt], bf[0][nt]);
                    mma_bf16(acc[2][mt][nt], a[2][mt], bf[1][nt]);
                    mma_bf16(acc[2][mt][nt], a[3][mt], bf[0][nt]);
                }
        }
        __syncthreads();   // stage st reusable at c+2
    }

    // Epilogue: direct float2 stores
    const int n0 = (wid & 3) * 16;
    #pragma unroll
    for (int mt = 0; mt < 2; mt++)
        #pragma unroll
        for (int nt = 0; nt < 2; nt++) {
            int row = l0 + m0 + mt * 16 + (lane >> 2);
            int col = h * 64 + n0 + nt * 8 + ((lane & 3) << 1);
            size_t base = ((size_t)b * LL + row) * DD + col;
            float* dp = acc[0][mt][nt];
            float* dn = acc[1][mt][nt];
            float* di = acc[2][mt][nt];
            *(float2*)(out + OUT_RE_OFF + base) =
                make_float2(dp[0] - dn[0], dp[1] - dn[1]);
            *(float2*)(out + OUT_RE_OFF + base + 8 * DD) =
                make_float2(dp[2] - dn[2], dp[3] - dn[3]);
            *(float2*)(out + OUT_IM_OFF + base) =
                make_float2(di[0], di[1]);
            *(float2*)(out + OUT_IM_OFF + base + 8 * DD) =
                make_float2(di[2], di[3]);
        }
}

// ---------------------------------------------------------------------------
extern "C" void kernel_launch(void* const* d_in, const int* in_sizes, int n_in,
                              void* d_out, int out_size)
{
    const float* xre = (const float*)d_in[0];
    const float* xim = (const float*)d_in[1];
    float* outp = (float*)d_out;

    const int smem2 = 2 * 8 * 1024 * 4;  // 65536
    cudaFuncSetAttribute(k1_scores, cudaFuncAttributeMaxDynamicSharedMemorySize, K1_SMEM);
    cudaFuncSetAttribute(k_softmax, cudaFuncAttributeMaxDynamicSharedMemorySize, smem2);
    cudaFuncSetAttribute(k3_out,    cudaFuncAttributeMaxDynamicSharedMemorySize, K3_SMEM);

    k0_split<<<2048, 256>>>(xre, xim);
    k1_scores<<<dim3(136, 1, 64), 256, K1_SMEM>>>(0);
    k_softmax<<<BB * LL, 256, smem2>>>(outp);
    k3_out<<<dim3(16, 64), 256, K3_SMEM>>>(outp);
}